// round 6
// baseline (speedup 1.0000x reference)
#include <cuda_runtime.h>
#include <cstdint>

// SobelEdge3D: out = sqrt(ed^2 + eh^2 + ew^2 + 1e-6), separable Sobel.
// Round-6: one cp.async.bulk (TMA/UBLKCP) per plane per CTA into a 4-deep
// shared ring; full/empty mbarrier pipeline; consumers read LDS.128 only.
// Each thread: 4 w (float4) x 2 h rows x 16 d outputs. Block = 128 threads.

constexpr int Wd  = 128;
constexpr int Hd  = 128;
constexpr int Dd  = 64;
constexpr int BCn = 32;            // B*C = 2*16
constexpr int HT  = 8;             // output h rows per block
constexpr int ND  = 16;            // d outputs per block
constexpr int HW  = Hd * Wd;
constexpr int NSLOT = 4;           // ring depth (planes in flight)
constexpr int SROWS = HT + 2;      // 10 tile rows: h0-1 .. h0+8
constexpr int ROWB  = Wd * 4;      // 512 B per row
constexpr int NPL   = ND + 2;      // 18 planes consumed per block

__device__ __forceinline__ float sqrt_approx(float v) {
    float r; asm("sqrt.approx.f32 %0,%1;" : "=f"(r) : "f"(v)); return r;
}
__device__ __forceinline__ void mbar_init(uint32_t a, uint32_t cnt) {
    asm volatile("mbarrier.init.shared.b64 [%0], %1;" :: "r"(a), "r"(cnt) : "memory");
}
__device__ __forceinline__ void mbar_expect_tx(uint32_t a, uint32_t bytes) {
    asm volatile("mbarrier.arrive.expect_tx.shared.b64 _, [%0], %1;"
                 :: "r"(a), "r"(bytes) : "memory");
}
__device__ __forceinline__ void mbar_arrive(uint32_t a) {
    asm volatile("mbarrier.arrive.shared.b64 _, [%0];" :: "r"(a) : "memory");
}
__device__ __forceinline__ void mbar_wait(uint32_t a, uint32_t parity) {
    asm volatile(
        "{\n\t.reg .pred P;\n"
        "W_%=:\n\t"
        "mbarrier.try_wait.parity.acquire.cta.shared::cta.b64 P, [%0], %1, 0x989680;\n\t"
        "@P bra.uni D_%=;\n\t"
        "bra.uni W_%=;\n"
        "D_%=:\n\t}"
        :: "r"(a), "r"(parity) : "memory");
}
__device__ __forceinline__ void bulk_g2s(uint32_t dst, const float* src,
                                         uint32_t bytes, uint32_t mbar) {
    asm volatile(
        "cp.async.bulk.shared::cta.global.mbarrier::complete_tx::bytes "
        "[%0], [%1], %2, [%3];"
        :: "r"(dst), "l"(src), "r"(bytes), "r"(mbar) : "memory");
}

__global__ __launch_bounds__(128, 5)
void sobel3d_kernel(const float* __restrict__ x, float* __restrict__ out)
{
    __shared__ alignas(16) float tile[NSLOT][SROWS][Wd];
    __shared__ alignas(8) unsigned long long mb[2 * NSLOT];  // [full0..3, empty0..3]

    const int tid = threadIdx.x;
    const int tx  = tid & 31;                 // w = 4*tx .. 4*tx+3
    const int ty  = tid >> 5;                 // 0..3 -> h rows h0+2ty, h0+2ty+1
    const int h0  = blockIdx.x * HT;
    const int d0  = blockIdx.y * ND;

    const float* __restrict__ xb = x   + (size_t)blockIdx.z * (Dd * HW);
    float* __restrict__       ob = out + (size_t)blockIdx.z * (Dd * HW);

    const uint32_t tbase = (uint32_t)__cvta_generic_to_shared(tile);
    const uint32_t mbase = (uint32_t)__cvta_generic_to_shared(mb);
    auto full_a  = [&](int s) { return mbase + s * 8; };
    auto empty_a = [&](int s) { return mbase + (NSLOT + s) * 8; };

    if (tid == 0) {
        #pragma unroll
        for (int s = 0; s < NSLOT; ++s) {
            mbar_init(full_a(s), 1);       // producer arrive + tx bytes
            mbar_init(empty_a(s), 128);    // all threads arrive after consume
        }
    }
    __syncthreads();

    // Contiguous valid h-range for the bulk copy (pad rows zero-predicated on read).
    const int srow   = max(h0 - 1, 0);
    const int nrows  = min(h0 + HT, Hd - 1) - srow + 1;        // 9 or 10
    const uint32_t cbytes = nrows * ROWB;
    const uint32_t soff   = (srow - (h0 - 1)) * ROWB;          // 0 or 512
    const int gcol = srow * Wd;

    // Fill slot (k&3) with plane d0-1+k (address-clamped; validity handled on read).
    auto fill = [&](int k) {
        const int p  = d0 - 1 + k;
        const int pc = min(max(p, 0), Dd - 1);
        const int s  = k & (NSLOT - 1);
        mbar_expect_tx(full_a(s), cbytes);
        bulk_g2s(tbase + s * (SROWS * ROWB) + soff, xb + pc * HW + gcol,
                 cbytes, full_a(s));
    };

    const bool hm = (h0 > 0);                 // tile row 0 valid (global h0-1)
    const bool hp = (h0 + HT < Hd);           // tile row 9 valid (global h0+8)

    // Consume plane k from its slot: row transforms -> A/B/C (2 output rows).
    auto abc = [&](int k, float (&A)[2][4], float (&B)[2][4], float (&C)[2][4]) {
        const int s = k & (NSLOT - 1);
        mbar_wait(full_a(s), (k >> 2) & 1);
        const bool pv = (unsigned)(d0 - 1 + k) < (unsigned)Dd;
        float g[4][4], sm[4][4];
        #pragma unroll
        for (int r = 0; r < 4; ++r) {
            const int rt_ = (ty << 1) + r;    // tile row for global h0+2ty-1+r
            float4 q = *(const float4*)&tile[s][rt_][tx << 2];
            const bool rv = pv && !((rt_ == 0 && !hm) || (rt_ == SROWS - 1 && !hp));
            if (!rv) q = make_float4(0.f, 0.f, 0.f, 0.f);
            float lf = __shfl_up_sync(0xffffffffu, q.w, 1);
            float rt = __shfl_down_sync(0xffffffffu, q.x, 1);
            if (tx == 0)  lf = 0.f;           // zero pad w = -1
            if (tx == 31) rt = 0.f;           // zero pad w = 128
            g[r][0] = q.y - lf;
            g[r][1] = q.z - q.x;
            g[r][2] = q.w - q.y;
            g[r][3] = rt  - q.z;
            sm[r][0] = fmaf(2.f, q.x, lf  + q.y);
            sm[r][1] = fmaf(2.f, q.y, q.x + q.z);
            sm[r][2] = fmaf(2.f, q.z, q.y + q.w);
            sm[r][3] = fmaf(2.f, q.w, q.z + rt);
        }
        mbar_arrive(empty_a(s));              // slot consumed by this thread
        #pragma unroll
        for (int o = 0; o < 2; ++o)
            #pragma unroll
            for (int j = 0; j < 4; ++j) {
                A[o][j] = fmaf(2.f, g[o + 1][j], g[o][j] + g[o + 2][j]);
                B[o][j] = sm[o + 2][j] - sm[o][j];
                C[o][j] = fmaf(2.f, sm[o + 1][j], sm[o][j] + sm[o + 2][j]);
            }
    };

    // Refill slot of plane k+NSLOT (thread 0): wait empty completion of plane k.
    auto refill = [&](int k) {
        if (tid == 0 && k + NSLOT < NPL) {
            const int s = k & (NSLOT - 1);
            mbar_wait(empty_a(s), (k >> 2) & 1);
            fill(k + NSLOT);
        }
    };

    // Prologue: fill the ring.
    if (tid == 0) {
        #pragma unroll
        for (int k = 0; k < NSLOT; ++k) fill(k);
    }

    float a[2][4], b[2][4], c[2][4];
    float ed0[2][4], eh0[2][4], ed1[2][4], eh1[2][4], Cp[2][4], Cq[2][4];

    abc(0, a, b, c);                          // plane d0-1
    #pragma unroll
    for (int o = 0; o < 2; ++o)
        #pragma unroll
        for (int j = 0; j < 4; ++j) {
            ed0[o][j] = a[o][j]; eh0[o][j] = b[o][j]; Cp[o][j] = c[o][j];
        }
    refill(0);

    abc(1, a, b, c);                          // plane d0
    #pragma unroll
    for (int o = 0; o < 2; ++o)
        #pragma unroll
        for (int j = 0; j < 4; ++j) {
            ed0[o][j] = fmaf(2.f, a[o][j], ed0[o][j]);
            eh0[o][j] = fmaf(2.f, b[o][j], eh0[o][j]);
            ed1[o][j] = a[o][j]; eh1[o][j] = b[o][j]; Cq[o][j] = c[o][j];
        }
    refill(1);

    const int obase = d0 * HW + (h0 + (ty << 1)) * Wd + (tx << 2);

    #pragma unroll
    for (int i = 0; i < ND; ++i) {
        const int k = i + 2;                  // plane d0+i+1
        abc(k, a, b, c);

        #pragma unroll
        for (int o = 0; o < 2; ++o) {
            float res[4];
            #pragma unroll
            for (int j = 0; j < 4; ++j) {
                float ed = ed0[o][j] + a[o][j];
                float eh = eh0[o][j] + b[o][j];
                float ew = c[o][j] - Cp[o][j];
                float m  = fmaf(ew, ew, fmaf(eh, eh, fmaf(ed, ed, 1e-6f)));
                res[j] = sqrt_approx(m);
                ed0[o][j] = fmaf(2.f, a[o][j], ed1[o][j]);
                eh0[o][j] = fmaf(2.f, b[o][j], eh1[o][j]);
                ed1[o][j] = a[o][j];
                eh1[o][j] = b[o][j];
                Cp[o][j]  = Cq[o][j];
                Cq[o][j]  = c[o][j];
            }
            *(float4*)(ob + obase + i * HW + o * Wd) =
                make_float4(res[0], res[1], res[2], res[3]);
        }
        refill(k);
    }
}

extern "C" void kernel_launch(void* const* d_in, const int* in_sizes, int n_in,
                              void* d_out, int out_size)
{
    const float* x = (const float*)d_in[0];
    float* out = (float*)d_out;
    dim3 grid(Hd / HT, Dd / ND, BCn);   // (16, 4, 32) = 2048 blocks
    dim3 block(128);                    // 4 warps; thread = 4w x 2h x 16d
    sobel3d_kernel<<<grid, block>>>(x, out);
}

// round 7
// speedup vs baseline: 1.2957x; 1.2957x over previous
#include <cuda_runtime.h>
#include <cstdint>

// SobelEdge3D: out = sqrt(ed^2 + eh^2 + ew^2 + 1e-6), separable Sobel.
// Round-7: R5 skeleton (private-slot cp.async ring, no cross-thread sync),
// ring depth 4 (prefetch distance 3), refill issued between smem reads and
// the FP stage. Each thread: 4 w (float4) x 2 h rows x 16 d outputs.

constexpr int Wd  = 128;
constexpr int Hd  = 128;
constexpr int Dd  = 64;
constexpr int BCn = 32;          // B*C = 2*16
constexpr int HT  = 8;           // h rows per block (ty 0..3, 2 rows each)
constexpr int ND  = 16;          // d outputs per block
constexpr int HW  = Hd * Wd;
constexpr int NSLOT = 4;         // smem ring depth (planes in flight)

__device__ __forceinline__ float sqrt_approx(float v) {
    float r; asm("sqrt.approx.f32 %0,%1;" : "=f"(r) : "f"(v)); return r;
}
__device__ __forceinline__ void cp16(uint32_t dst, const float* src, int sz) {
    // 16B async copy; sz=0 => zero-fill (padding rows/planes).
    asm volatile("cp.async.ca.shared.global [%0], [%1], 16, %2;"
                 :: "r"(dst), "l"(src), "r"(sz));
}
__device__ __forceinline__ void cp_commit() {
    asm volatile("cp.async.commit_group;" ::: "memory");
}
__device__ __forceinline__ void cp_wait3() {
    asm volatile("cp.async.wait_group 3;" ::: "memory");
}

__global__ __launch_bounds__(128, 5)
void sobel3d_kernel(const float* __restrict__ x, float* __restrict__ out)
{
    // ring[slot][row][tid]: each thread's 4 rows of one plane, 16B each.
    __shared__ float4 ring[NSLOT][4][128];

    const int tid = threadIdx.x;
    const int tx  = tid & 31;                 // w = 4*tx .. 4*tx+3
    const int ty  = tid >> 5;                 // 0..3
    const int ha  = blockIdx.x * HT + (ty << 1);  // first of 2 output h rows
    const int d0  = blockIdx.y * ND;

    const float* __restrict__ xb = x   + (size_t)blockIdx.z * (Dd * HW);
    float* __restrict__       ob = out + (size_t)blockIdx.z * (Dd * HW);

    const uint32_t sb = (uint32_t)__cvta_generic_to_shared(ring) + tid * 16;

    // Issue one plane's 4 rows (ha-1..ha+2) into ring slot k&3; always commits.
    auto cp_plane = [&](int k) {                  // k = plane index d0-1+k
        const int p  = d0 - 1 + k;
        const int pc = min(max(p, 0), Dd - 1);    // clamped address (safety)
        const bool pv = (unsigned)p < (unsigned)Dd && k < ND + 2;
        const float* pb = xb + pc * HW + (tx << 2);
        const uint32_t d = sb + (k & (NSLOT - 1)) * (4 * 128 * 16);
        #pragma unroll
        for (int r = 0; r < 4; ++r) {
            const int hh = ha - 1 + r;
            const int hc = min(max(hh, 0), Hd - 1);
            const int sz = (pv && (unsigned)hh < (unsigned)Hd) ? 16 : 0;
            cp16(d + r * 2048, pb + hc * Wd, sz);
        }
        cp_commit();
    };

    // Read slot k's 4 raw rows into registers (wait first).
    auto ldrows = [&](int k, float4 (&R)[4]) {
        cp_wait3();
        const int s = k & (NSLOT - 1);
        #pragma unroll
        for (int r = 0; r < 4; ++r) R[r] = ring[s][r][tid];
    };

    // Row transforms + fold to A/B/C for the 2 output rows.
    auto abc = [&](const float4 (&R)[4],
                   float (&A)[2][4], float (&B)[2][4], float (&C)[2][4]) {
        float g[4][4], s[4][4];
        #pragma unroll
        for (int r = 0; r < 4; ++r) {
            float4 q = R[r];
            float lf = __shfl_up_sync(0xffffffffu, q.w, 1);
            float rt = __shfl_down_sync(0xffffffffu, q.x, 1);
            if (tx == 0)  lf = 0.f;     // zero pad w = -1
            if (tx == 31) rt = 0.f;     // zero pad w = 128
            g[r][0] = q.y - lf;
            g[r][1] = q.z - q.x;
            g[r][2] = q.w - q.y;
            g[r][3] = rt  - q.z;
            s[r][0] = fmaf(2.f, q.x, lf  + q.y);
            s[r][1] = fmaf(2.f, q.y, q.x + q.z);
            s[r][2] = fmaf(2.f, q.z, q.y + q.w);
            s[r][3] = fmaf(2.f, q.w, q.z + rt);
        }
        #pragma unroll
        for (int o = 0; o < 2; ++o) {
            #pragma unroll
            for (int j = 0; j < 4; ++j) {
                A[o][j] = fmaf(2.f, g[o + 1][j], g[o][j] + g[o + 2][j]);
                B[o][j] = s[o + 2][j] - s[o][j];
                C[o][j] = fmaf(2.f, s[o + 1][j], s[o][j] + s[o + 2][j]);
            }
        }
    };

    float4 R[4];
    float a[2][4], b[2][4], c[2][4];
    float ed0[2][4], eh0[2][4], ed1[2][4], eh1[2][4], Cp[2][4], Cq[2][4];

    // Prologue: fill ring with planes k=0..3 (d0-1 .. d0+2).
    cp_plane(0); cp_plane(1); cp_plane(2); cp_plane(3);

    // Consume k=0 (plane d0-1); refill k=4.
    ldrows(0, R);
    cp_plane(4);
    abc(R, a, b, c);
    #pragma unroll
    for (int o = 0; o < 2; ++o)
        #pragma unroll
        for (int j = 0; j < 4; ++j) {
            ed0[o][j] = a[o][j]; eh0[o][j] = b[o][j]; Cp[o][j] = c[o][j];
        }

    // Consume k=1 (plane d0); refill k=5.
    ldrows(1, R);
    cp_plane(5);
    abc(R, a, b, c);
    #pragma unroll
    for (int o = 0; o < 2; ++o)
        #pragma unroll
        for (int j = 0; j < 4; ++j) {
            ed0[o][j] = fmaf(2.f, a[o][j], ed0[o][j]);
            eh0[o][j] = fmaf(2.f, b[o][j], eh0[o][j]);
            ed1[o][j] = a[o][j]; eh1[o][j] = b[o][j]; Cq[o][j] = c[o][j];
        }

    const int obase = d0 * HW + ha * Wd + (tx << 2);

    // Steady state: iter i consumes k=i+2 (plane d0+1+i), refills k=i+6.
    #pragma unroll
    for (int i = 0; i < ND; ++i) {
        ldrows(i + 2, R);
        cp_plane(i + 6);                 // dummy (sz=0) past the last needed plane
        abc(R, a, b, c);

        #pragma unroll
        for (int o = 0; o < 2; ++o) {
            float res[4];
            #pragma unroll
            for (int j = 0; j < 4; ++j) {
                float ed = ed0[o][j] + a[o][j];
                float eh = eh0[o][j] + b[o][j];
                float ew = c[o][j] - Cp[o][j];
                float m  = fmaf(ew, ew, fmaf(eh, eh, fmaf(ed, ed, 1e-6f)));
                res[j] = sqrt_approx(m);
                ed0[o][j] = fmaf(2.f, a[o][j], ed1[o][j]);
                eh0[o][j] = fmaf(2.f, b[o][j], eh1[o][j]);
                ed1[o][j] = a[o][j];
                eh1[o][j] = b[o][j];
                Cp[o][j]  = Cq[o][j];
                Cq[o][j]  = c[o][j];
            }
            *(float4*)(ob + obase + i * HW + o * Wd) =
                make_float4(res[0], res[1], res[2], res[3]);
        }
    }
}

extern "C" void kernel_launch(void* const* d_in, const int* in_sizes, int n_in,
                              void* d_out, int out_size)
{
    const float* x = (const float*)d_in[0];
    float* out = (float*)d_out;
    dim3 grid(Hd / HT, Dd / ND, BCn);   // (16, 4, 32) = 2048 blocks
    dim3 block(128);                    // 4 warps; thread = 4w x 2h x 16d
    sobel3d_kernel<<<grid, block>>>(x, out);
}

// round 9
// speedup vs baseline: 1.3994x; 1.0800x over previous
#include <cuda_runtime.h>
#include <cstdint>

// SobelEdge3D: out = sqrt(ed^2 + eh^2 + ew^2 + 1e-6), separable Sobel.
// Round-8 (resubmit; prior run died to container infra, kernel never ran):
// shared plane tile (10 unique halo rows, disjointly produced by all
// 128 threads -> 2.5 cp.async/thread/plane instead of 4), depth-4 ring,
// one __syncthreads per plane, zero-fill padding via cp.async src-size 0.
// Each thread consumes 4 rows -> 2 output h rows x 4 w x 16 d.

constexpr int Wd  = 128;
constexpr int Hd  = 128;
constexpr int Dd  = 64;
constexpr int BCn = 32;          // B*C = 2*16
constexpr int HT  = 8;           // output h rows per block
constexpr int ND  = 16;          // d outputs per block
constexpr int HW  = Hd * Wd;
constexpr int NSLOT = 4;         // ring depth
constexpr int SROWS = HT + 2;    // 10 tile rows: h0-1 .. h0+8
constexpr int NPL   = ND + 2;    // 18 planes consumed per block

__device__ __forceinline__ float sqrt_approx(float v) {
    float r; asm("sqrt.approx.f32 %0,%1;" : "=f"(r) : "f"(v)); return r;
}
__device__ __forceinline__ void cp16(uint32_t dst, const float* src, int sz) {
    // 16B async copy; sz=0 => zero-fill (padding rows/planes).
    asm volatile("cp.async.ca.shared.global [%0], [%1], 16, %2;"
                 :: "r"(dst), "l"(src), "r"(sz));
}
__device__ __forceinline__ void cp_commit() {
    asm volatile("cp.async.commit_group;" ::: "memory");
}
__device__ __forceinline__ void cp_wait2() {
    asm volatile("cp.async.wait_group 2;" ::: "memory");
}

__global__ __launch_bounds__(128, 5)
void sobel3d_kernel(const float* __restrict__ x, float* __restrict__ out)
{
    // Shared plane ring: 10 unique halo rows per plane, full 128-wide.
    __shared__ alignas(16) float tile[NSLOT][SROWS][Wd];   // 20 KB

    const int tid = threadIdx.x;
    const int tx  = tid & 31;                 // w = 4*tx .. 4*tx+3
    const int ty  = tid >> 5;                 // 0..3
    const int h0  = blockIdx.x * HT;
    const int d0  = blockIdx.y * ND;
    const int ha  = h0 + (ty << 1);           // first of this thread's 2 h rows

    const float* __restrict__ xb = x   + (size_t)blockIdx.z * (Dd * HW);
    float* __restrict__       ob = out + (size_t)blockIdx.z * (Dd * HW);

    const uint32_t tb = (uint32_t)__cvta_generic_to_shared(tile);

    // Produce plane k (= d-index d0-1+k) into slot k&3.
    // Thread tid writes rows ty+4j (j=0,1[,2 if ty<2]) at column tx (16B).
    auto cp_plane = [&](int k) {
        if (k >= NPL) { cp_commit(); return; }     // tail: empty group
        const int p  = d0 - 1 + k;
        const int pc = min(max(p, 0), Dd - 1);     // clamped address (safety)
        const bool pv = (unsigned)p < (unsigned)Dd;
        const float* pb = xb + pc * HW + (tx << 2);
        const uint32_t db = tb + (k & (NSLOT - 1)) * (SROWS * Wd * 4) + (tx << 4);
        #pragma unroll
        for (int j = 0; j < 3; ++j) {
            const int r = ty + 4 * j;              // tile row
            if (r < SROWS) {
                const int hh = h0 - 1 + r;         // global h of tile row r
                const int hc = min(max(hh, 0), Hd - 1);
                const int sz = (pv && (unsigned)hh < (unsigned)Hd) ? 16 : 0;
                cp16(db + r * (Wd * 4), pb + hc * Wd, sz);
            }
        }
        cp_commit();
    };

    // Consume plane k: wait, block-sync, read 4 rows, fold to A/B/C.
    auto abc = [&](int k, float (&A)[2][4], float (&B)[2][4], float (&C)[2][4]) {
        cp_wait2();
        __syncthreads();
        const int s = k & (NSLOT - 1);
        float g[4][4], sm[4][4];
        #pragma unroll
        for (int r = 0; r < 4; ++r) {
            // tile row (2ty + r) = global h row ha-1+r (pads already zeroed)
            float4 q = *(const float4*)&tile[s][(ty << 1) + r][tx << 2];
            float lf = __shfl_up_sync(0xffffffffu, q.w, 1);
            float rt = __shfl_down_sync(0xffffffffu, q.x, 1);
            if (tx == 0)  lf = 0.f;     // zero pad w = -1
            if (tx == 31) rt = 0.f;     // zero pad w = 128
            g[r][0] = q.y - lf;
            g[r][1] = q.z - q.x;
            g[r][2] = q.w - q.y;
            g[r][3] = rt  - q.z;
            sm[r][0] = fmaf(2.f, q.x, lf  + q.y);
            sm[r][1] = fmaf(2.f, q.y, q.x + q.z);
            sm[r][2] = fmaf(2.f, q.z, q.y + q.w);
            sm[r][3] = fmaf(2.f, q.w, q.z + rt);
        }
        #pragma unroll
        for (int o = 0; o < 2; ++o) {
            #pragma unroll
            for (int j = 0; j < 4; ++j) {
                A[o][j] = fmaf(2.f, g[o + 1][j], g[o][j] + g[o + 2][j]);
                B[o][j] = sm[o + 2][j] - sm[o][j];
                C[o][j] = fmaf(2.f, sm[o + 1][j], sm[o][j] + sm[o + 2][j]);
            }
        }
    };

    float a[2][4], b[2][4], c[2][4];
    float ed0[2][4], eh0[2][4], ed1[2][4], eh1[2][4], Cp[2][4], Cq[2][4];

    // Prologue: planes k = 0, 1, 2 in flight (prefetch distance 3).
    cp_plane(0); cp_plane(1); cp_plane(2);

    // Consume k=0 (plane d0-1); refill k=3.
    abc(0, a, b, c);
    #pragma unroll
    for (int o = 0; o < 2; ++o)
        #pragma unroll
        for (int j = 0; j < 4; ++j) {
            ed0[o][j] = a[o][j]; eh0[o][j] = b[o][j]; Cp[o][j] = c[o][j];
        }
    cp_plane(3);

    // Consume k=1 (plane d0); refill k=4.
    abc(1, a, b, c);
    #pragma unroll
    for (int o = 0; o < 2; ++o)
        #pragma unroll
        for (int j = 0; j < 4; ++j) {
            ed0[o][j] = fmaf(2.f, a[o][j], ed0[o][j]);
            eh0[o][j] = fmaf(2.f, b[o][j], eh0[o][j]);
            ed1[o][j] = a[o][j]; eh1[o][j] = b[o][j]; Cq[o][j] = c[o][j];
        }
    cp_plane(4);

    const int obase = d0 * HW + ha * Wd + (tx << 2);

    // Steady state: iter i consumes k=i+2 (plane d0+1+i), refills k=i+5.
    #pragma unroll
    for (int i = 0; i < ND; ++i) {
        abc(i + 2, a, b, c);

        #pragma unroll
        for (int o = 0; o < 2; ++o) {
            float res[4];
            #pragma unroll
            for (int j = 0; j < 4; ++j) {
                float ed = ed0[o][j] + a[o][j];
                float eh = eh0[o][j] + b[o][j];
                float ew = c[o][j] - Cp[o][j];
                float m  = fmaf(ew, ew, fmaf(eh, eh, fmaf(ed, ed, 1e-6f)));
                res[j] = sqrt_approx(m);
                ed0[o][j] = fmaf(2.f, a[o][j], ed1[o][j]);
                eh0[o][j] = fmaf(2.f, b[o][j], eh1[o][j]);
                ed1[o][j] = a[o][j];
                eh1[o][j] = b[o][j];
                Cp[o][j]  = Cq[o][j];
                Cq[o][j]  = c[o][j];
            }
            *(float4*)(ob + obase + i * HW + o * Wd) =
                make_float4(res[0], res[1], res[2], res[3]);
        }
        cp_plane(i + 5);            // empty group past the last needed plane
    }
}

extern "C" void kernel_launch(void* const* d_in, const int* in_sizes, int n_in,
                              void* d_out, int out_size)
{
    const float* x = (const float*)d_in[0];
    float* out = (float*)d_out;
    dim3 grid(Hd / HT, Dd / ND, BCn);   // (16, 4, 32) = 2048 blocks
    dim3 block(128);                    // 4 warps; thread = 4w x 2h x 16d
    sobel3d_kernel<<<grid, block>>>(x, out);
}